// round 7
// baseline (speedup 1.0000x reference)
#include <cuda_runtime.h>

#define HH 512
#define WW 512
#define NPIX (HH*WW)
#define BS 16

// Per-(batch,direction) projection params: Au(3), Av(3), A0(3), c(3)
__device__ float g_params[BS * 2][12];
__device__ int g_maskmode;  // 0 = 4-byte elements, 1 = 1-byte elements

__global__ void setup_kernel(const float* __restrict__ R0, const float* __restrict__ t0,
                             const float* __restrict__ R1, const float* __restrict__ t1,
                             const float* __restrict__ K,
                             const unsigned int* __restrict__ mask_probe,
                             float* __restrict__ out, int out_size)
{
    int t = threadIdx.x;
    if (t < out_size && t < 32) out[t] = 0.0f;

    if (t == 0) {
        bool sawFloat = false, sawBig = false;
        for (int i = 0; i < 16; i++) {
            unsigned int w = mask_probe[i];
            if (w == 0x3f800000u) sawFloat = true;
            else if (w > 1u) sawBig = true;
        }
        g_maskmode = sawFloat ? 0 : (sawBig ? 1 : 0);
    }

    if (t >= 32) return;
    int b = t >> 1;
    int dir = t & 1;

    float k[9];
    #pragma unroll
    for (int i = 0; i < 9; i++) k[i] = K[i];
    float det = k[0]*(k[4]*k[8]-k[5]*k[7]) - k[1]*(k[3]*k[8]-k[5]*k[6]) + k[2]*(k[3]*k[7]-k[4]*k[6]);
    float rdet = 1.0f / det;
    float ki[9];
    ki[0]=(k[4]*k[8]-k[5]*k[7])*rdet; ki[1]=(k[2]*k[7]-k[1]*k[8])*rdet; ki[2]=(k[1]*k[5]-k[2]*k[4])*rdet;
    ki[3]=(k[5]*k[6]-k[3]*k[8])*rdet; ki[4]=(k[0]*k[8]-k[2]*k[6])*rdet; ki[5]=(k[2]*k[3]-k[0]*k[5])*rdet;
    ki[6]=(k[3]*k[7]-k[4]*k[6])*rdet; ki[7]=(k[1]*k[6]-k[0]*k[7])*rdet; ki[8]=(k[0]*k[4]-k[1]*k[3])*rdet;

    const float* Ra = dir ? (R1 + 9*b) : (R0 + 9*b);
    const float* Rb = dir ? (R0 + 9*b) : (R1 + 9*b);
    const float* ta = dir ? (t1 + 3*b) : (t0 + 3*b);
    const float* tb = dir ? (t0 + 3*b) : (t1 + 3*b);

    float M3[9];
    #pragma unroll
    for (int i = 0; i < 3; i++)
        #pragma unroll
        for (int j = 0; j < 3; j++) {
            float s = 0.0f;
            #pragma unroll
            for (int d = 0; d < 3; d++) s += Rb[i*3+d] * Ra[j*3+d];
            M3[i*3+j] = s;
        }
    float M[9];
    #pragma unroll
    for (int i = 0; i < 3; i++)
        #pragma unroll
        for (int j = 0; j < 3; j++) {
            float s = 0.0f;
            #pragma unroll
            for (int d = 0; d < 3; d++) s += k[i*3+d] * M3[d*3+j];
            M[i*3+j] = s;
        }
    float c[3];
    #pragma unroll
    for (int i = 0; i < 3; i++) {
        float s = 0.0f;
        #pragma unroll
        for (int d = 0; d < 3; d++) s += k[i*3+d]*tb[d] - M[i*3+d]*ta[d];
        c[i] = s;
    }
    float G[9];
    #pragma unroll
    for (int i = 0; i < 3; i++)
        #pragma unroll
        for (int j = 0; j < 3; j++) {
            float s = 0.0f;
            #pragma unroll
            for (int d = 0; d < 3; d++) s += M[i*3+d] * ki[d*3+j];
            G[i*3+j] = s;
        }

    float* P = g_params[t];
    P[0] = G[0]; P[1] = G[3]; P[2] = G[6];
    P[3] = G[1]; P[4] = G[4]; P[5] = G[7];
    P[6] = G[2]; P[7] = G[5]; P[8] = G[8];
    P[9] = c[0]; P[10] = c[1]; P[11] = c[2];
}

__inline__ __device__ float warp_sum(float v) {
    #pragma unroll
    for (int o = 16; o > 0; o >>= 1) v += __shfl_down_sync(0xffffffffu, v, o);
    return v;
}

__inline__ __device__ float fast_rcp(float x) {
    float r;
    asm("rcp.approx.ftz.f32 %0, %1;" : "=f"(r) : "f"(x));
    return r;
}

__global__ __launch_bounds__(256, 4)
void loss_kernel(const float* __restrict__ d0, const float* __restrict__ d1,
                 const float* __restrict__ r0, const float* __restrict__ r1,
                 const void* __restrict__ m0, const void* __restrict__ m1,
                 float* __restrict__ out)
{
    const int b   = blockIdx.y;
    const int dir = blockIdx.z;

    const float* ds = dir ? d1 : d0;
    const float* dd = dir ? d0 : d1;
    const float* rs = dir ? r1 : r0;
    const float* rd = dir ? r0 : r1;
    const void*  ms = dir ? m1 : m0;

    const float* P = g_params[b*2 + dir];
    const float Au0=P[0], Au1=P[1], Au2=P[2];
    const float Av0=P[3], Av1=P[4], Av2=P[5];
    const float A00=P[6], A01=P[7], A02=P[8];
    const float c0 =P[9], c1 =P[10], c2 =P[11];
    const int mode = g_maskmode;

    const int base  = b * NPIX;
    const int base3 = b * 3 * NPIX;

    const float4* dsv  = (const float4*)(ds + base);
    const float4* rsv0 = (const float4*)(rs + base3);
    const float4* rsv1 = (const float4*)(rs + base3 + NPIX);
    const float4* rsv2 = (const float4*)(rs + base3 + 2*NPIX);

    const float* ddp = dd + base;          // dest depth image
    const float* ch0 = rd + base3;         // dest rgb channel planes
    const float* ch1 = rd + base3 + NPIX;
    const float* ch2 = rd + base3 + 2*NPIX;

    float sd = 0.0f, sr = 0.0f;
    const int nq = NPIX / 4;
    const int stride = gridDim.x * blockDim.x;

    for (int q = blockIdx.x * blockDim.x + threadIdx.x; q < nq; q += stride) {
        const int p0 = q << 2;

        // ---- coherent streaming loads (single batch at top) ----
        float4 dep4 = __ldcs(dsv + q);
        float dep[4] = {dep4.x, dep4.y, dep4.z, dep4.w};

        bool m[4];
        if (mode) {
            uchar4 u4 = __ldcs((const uchar4*)((const unsigned char*)ms + base) + q);
            m[0] = u4.x != 0; m[1] = u4.y != 0; m[2] = u4.z != 0; m[3] = u4.w != 0;
        } else {
            uint4 u4 = __ldcs((const uint4*)((const unsigned int*)ms + base) + q);
            m[0] = u4.x != 0u; m[1] = u4.y != 0u; m[2] = u4.z != 0u; m[3] = u4.w != 0u;
        }

        float4 s0 = __ldcs(rsv0 + q);
        float4 s1 = __ldcs(rsv1 + q);
        float4 s2 = __ldcs(rsv2 + q);
        float src0[4] = {s0.x,s0.y,s0.z,s0.w};
        float src1[4] = {s1.x,s1.y,s1.z,s1.w};
        float src2[4] = {s2.x,s2.y,s2.z,s2.w};

        const float v  = (float)(p0 >> 9);
        const float u0 = (float)(p0 & 511);
        const float bX = fmaf(Av0, v, A00);
        const float bY = fmaf(Av1, v, A01);
        const float bZ = fmaf(Av2, v, A02);

        // ---- per pixel: project, then ONE gather epoch (depth + rgb together) ----
        #pragma unroll
        for (int i = 0; i < 4; i++) {
            if (!m[i]) continue;           // 70% taken; warp-level ~always

            float u = u0 + (float)i;
            float X  = fmaf(dep[i], fmaf(Au0, u, bX), c0);
            float Y  = fmaf(dep[i], fmaf(Au1, u, bY), c1);
            float Z  = fmaf(dep[i], fmaf(Au2, u, bZ), c2);

            float inv = fast_rcp(fmaxf(Z, 0.0f) + 1e-12f);
            float xs = fmaf(X * inv, 512.0f / 511.0f, -0.5f);
            float ys = fmaf(Y * inv, 512.0f / 511.0f, -0.5f);
            xs = fminf(fmaxf(xs, 0.0f), 511.0f);
            ys = fminf(fmaxf(ys, 0.0f), 511.0f);

            float x0f = floorf(xs), y0f = floorf(ys);
            float fx = xs - x0f, fy = ys - y0f;
            int x0 = (int)x0f, y0 = (int)y0f;
            int dx  = (x0 < WW - 1) ? 1 : 0;
            int dyW = (y0 < HH - 1) ? WW : 0;
            int a00 = y0 * WW + x0;        // offset within one image plane
            int a01 = a00 + dx;
            int a10 = a00 + dyW;
            int a11 = a10 + dx;

            // 16 independent gathers: depth + 3 rgb channels, one epoch
            float d00 = __ldg(ddp + a00), d01 = __ldg(ddp + a01);
            float d10 = __ldg(ddp + a10), d11 = __ldg(ddp + a11);
            float r00 = __ldg(ch0 + a00), r01 = __ldg(ch0 + a01);
            float r10 = __ldg(ch0 + a10), r11 = __ldg(ch0 + a11);
            float gg00 = __ldg(ch1 + a00), gg01 = __ldg(ch1 + a01);
            float gg10 = __ldg(ch1 + a10), gg11 = __ldg(ch1 + a11);
            float b00 = __ldg(ch2 + a00), b01 = __ldg(ch2 + a01);
            float b10 = __ldg(ch2 + a10), b11 = __ldg(ch2 + a11);

            float ofx = 1.0f - fx, ofy = 1.0f - fy;
            float w00 = ofx*ofy, w01 = fx*ofy, w10 = ofx*fy, w11 = fx*fy;

            float dsm = w00*d00 + w01*d01 + w10*d10 + w11*d11;
            float ld = fabsf(Z - dsm);
            bool pass = ld < 0.1f;

            float smr = w00*r00 + w01*r01 + w10*r10 + w11*r11;
            float smg = w00*gg00 + w01*gg01 + w10*gg10 + w11*gg11;
            float smb = w00*b00 + w01*b01 + w10*b10 + w11*b11;
            float lr = fabsf(src0[i] - smr) + fabsf(src1[i] - smg) + fabsf(src2[i] - smb);

            sd += pass ? ld : 0.0f;
            sr += pass ? lr * (1.0f / 3.0f) : 0.0f;
        }
    }

    sd = warp_sum(sd);
    sr = warp_sum(sr);
    __shared__ float sD[8], sR[8];
    int lane = threadIdx.x & 31, wid = threadIdx.x >> 5;
    if (lane == 0) { sD[wid] = sd; sR[wid] = sr; }
    __syncthreads();
    if (threadIdx.x == 0) {
        float td = 0.0f, tr = 0.0f;
        #pragma unroll
        for (int i = 0; i < 8; i++) { td += sD[i]; tr += sR[i]; }
        const float invN = 1.0f / (float)NPIX;
        atomicAdd(out + b,      td * invN);
        atomicAdd(out + 16 + b, tr * invN);
    }
}

extern "C" void kernel_launch(void* const* d_in, const int* in_sizes, int n_in,
                              void* d_out, int out_size)
{
    const float* depth0 = (const float*)d_in[0];
    const float* depth1 = (const float*)d_in[1];
    const float* R0     = (const float*)d_in[2];
    const float* t0     = (const float*)d_in[3];
    const float* R1     = (const float*)d_in[4];
    const float* t1     = (const float*)d_in[5];
    const float* rgb0   = (const float*)d_in[6];
    const float* rgb1   = (const float*)d_in[7];
    const void*  mask0  = d_in[8];
    const void*  mask1  = d_in[9];
    const float* K      = (const float*)d_in[10];
    float* out = (float*)d_out;

    setup_kernel<<<1, 64>>>(R0, t0, R1, t1, K, (const unsigned int*)mask0, out, out_size);

    dim3 grid(64, BS, 2);
    loss_kernel<<<grid, 256>>>(depth0, depth1, rgb0, rgb1, mask0, mask1, out);
}

// round 8
// speedup vs baseline: 1.6708x; 1.6708x over previous
#include <cuda_runtime.h>

#define HH 512
#define WW 512
#define NPIX (HH*WW)
#define BS 16

// Per-(batch,direction) projection params: Au(3), Av(3), A0(3), c(3)
__device__ float g_params[BS * 2][12];
__device__ int g_maskmode;  // 0 = 4-byte elements, 1 = 1-byte elements

__global__ void setup_kernel(const float* __restrict__ R0, const float* __restrict__ t0,
                             const float* __restrict__ R1, const float* __restrict__ t1,
                             const float* __restrict__ K,
                             const unsigned int* __restrict__ mask_probe,
                             float* __restrict__ out, int out_size)
{
    int t = threadIdx.x;
    if (t < out_size && t < 32) out[t] = 0.0f;

    if (t == 0) {
        bool sawFloat = false, sawBig = false;
        for (int i = 0; i < 16; i++) {
            unsigned int w = mask_probe[i];
            if (w == 0x3f800000u) sawFloat = true;
            else if (w > 1u) sawBig = true;
        }
        g_maskmode = sawFloat ? 0 : (sawBig ? 1 : 0);
    }

    if (t >= 32) return;
    int b = t >> 1;
    int dir = t & 1;

    float k[9];
    #pragma unroll
    for (int i = 0; i < 9; i++) k[i] = K[i];
    float det = k[0]*(k[4]*k[8]-k[5]*k[7]) - k[1]*(k[3]*k[8]-k[5]*k[6]) + k[2]*(k[3]*k[7]-k[4]*k[6]);
    float rdet = 1.0f / det;
    float ki[9];
    ki[0]=(k[4]*k[8]-k[5]*k[7])*rdet; ki[1]=(k[2]*k[7]-k[1]*k[8])*rdet; ki[2]=(k[1]*k[5]-k[2]*k[4])*rdet;
    ki[3]=(k[5]*k[6]-k[3]*k[8])*rdet; ki[4]=(k[0]*k[8]-k[2]*k[6])*rdet; ki[5]=(k[2]*k[3]-k[0]*k[5])*rdet;
    ki[6]=(k[3]*k[7]-k[4]*k[6])*rdet; ki[7]=(k[1]*k[6]-k[0]*k[7])*rdet; ki[8]=(k[0]*k[4]-k[1]*k[3])*rdet;

    const float* Ra = dir ? (R1 + 9*b) : (R0 + 9*b);
    const float* Rb = dir ? (R0 + 9*b) : (R1 + 9*b);
    const float* ta = dir ? (t1 + 3*b) : (t0 + 3*b);
    const float* tb = dir ? (t0 + 3*b) : (t1 + 3*b);

    float M3[9];
    #pragma unroll
    for (int i = 0; i < 3; i++)
        #pragma unroll
        for (int j = 0; j < 3; j++) {
            float s = 0.0f;
            #pragma unroll
            for (int d = 0; d < 3; d++) s += Rb[i*3+d] * Ra[j*3+d];
            M3[i*3+j] = s;
        }
    float M[9];
    #pragma unroll
    for (int i = 0; i < 3; i++)
        #pragma unroll
        for (int j = 0; j < 3; j++) {
            float s = 0.0f;
            #pragma unroll
            for (int d = 0; d < 3; d++) s += k[i*3+d] * M3[d*3+j];
            M[i*3+j] = s;
        }
    float c[3];
    #pragma unroll
    for (int i = 0; i < 3; i++) {
        float s = 0.0f;
        #pragma unroll
        for (int d = 0; d < 3; d++) s += k[i*3+d]*tb[d] - M[i*3+d]*ta[d];
        c[i] = s;
    }
    float G[9];
    #pragma unroll
    for (int i = 0; i < 3; i++)
        #pragma unroll
        for (int j = 0; j < 3; j++) {
            float s = 0.0f;
            #pragma unroll
            for (int d = 0; d < 3; d++) s += M[i*3+d] * ki[d*3+j];
            G[i*3+j] = s;
        }

    float* P = g_params[t];
    P[0] = G[0]; P[1] = G[3]; P[2] = G[6];
    P[3] = G[1]; P[4] = G[4]; P[5] = G[7];
    P[6] = G[2]; P[7] = G[5]; P[8] = G[8];
    P[9] = c[0]; P[10] = c[1]; P[11] = c[2];
}

__inline__ __device__ float warp_sum(float v) {
    #pragma unroll
    for (int o = 16; o > 0; o >>= 1) v += __shfl_down_sync(0xffffffffu, v, o);
    return v;
}

__inline__ __device__ float fast_rcp(float x) {
    float r;
    asm("rcp.approx.ftz.f32 %0, %1;" : "=f"(r) : "f"(x));
    return r;
}

__inline__ __device__ int load_mask_bits(const void* ms, int mode, int base, int q) {
    if (mode) {
        uchar4 u = __ldcs((const uchar4*)((const unsigned char*)ms + base) + q);
        return (u.x != 0) | ((u.y != 0) << 1) | ((u.z != 0) << 2) | ((u.w != 0) << 3);
    } else {
        uint4 u = __ldcs((const uint4*)((const unsigned int*)ms + base) + q);
        return (u.x != 0u) | ((u.y != 0u) << 1) | ((u.z != 0u) << 2) | ((u.w != 0u) << 3);
    }
}

__global__ __launch_bounds__(256, 4)
void loss_kernel(const float* __restrict__ d0, const float* __restrict__ d1,
                 const float* __restrict__ r0, const float* __restrict__ r1,
                 const void* __restrict__ m0, const void* __restrict__ m1,
                 float* __restrict__ out)
{
    const int b   = blockIdx.y;
    const int dir = blockIdx.z;

    const float* ds = dir ? d1 : d0;
    const float* dd = dir ? d0 : d1;
    const float* rs = dir ? r1 : r0;
    const float* rd = dir ? r0 : r1;
    const void*  ms = dir ? m1 : m0;

    const float* P = g_params[b*2 + dir];
    const float Au0=P[0], Au1=P[1], Au2=P[2];
    const float Av0=P[3], Av1=P[4], Av2=P[5];
    const float A00=P[6], A01=P[7], A02=P[8];
    const float c0 =P[9], c1 =P[10], c2 =P[11];
    const int mode = g_maskmode;

    const int base  = b * NPIX;
    const int base3 = b * 3 * NPIX;

    const float4* dsv = (const float4*)(ds + base);

    float sd = 0.0f, sr = 0.0f;
    const int nq = NPIX / 4;
    const int stride = gridDim.x * blockDim.x;

    int q = blockIdx.x * blockDim.x + threadIdx.x;
    float4 dep4;
    int mb = 0;
    if (q < nq) {
        dep4 = __ldcs(dsv + q);
        mb = load_mask_bits(ms, mode, base, q);
    }

    for (; q < nq; ) {
        const int p0 = q << 2;
        float dep[4] = {dep4.x, dep4.y, dep4.z, dep4.w};

        const float v  = (float)(p0 >> 9);
        const float u0 = (float)(p0 & 511);
        const float bX = fmaf(Av0, v, A00);
        const float bY = fmaf(Av1, v, A01);
        const float bZ = fmaf(Av2, v, A02);

        // ---- projections (batched, ILP=4) ----
        float Z[4], fx[4], fy[4];
        int i00[4], dx[4], dyW[4];
        #pragma unroll
        for (int i = 0; i < 4; i++) {
            float u = u0 + (float)i;
            float X  = fmaf(dep[i], fmaf(Au0, u, bX), c0);
            float Y  = fmaf(dep[i], fmaf(Au1, u, bY), c1);
            float Zi = fmaf(dep[i], fmaf(Au2, u, bZ), c2);
            Z[i] = Zi;

            float inv = fast_rcp(fmaxf(Zi, 0.0f) + 1e-12f);
            float xs = fmaf(X * inv, 512.0f / 511.0f, -0.5f);
            float ys = fmaf(Y * inv, 512.0f / 511.0f, -0.5f);
            xs = fminf(fmaxf(xs, 0.0f), 511.0f);
            ys = fminf(fmaxf(ys, 0.0f), 511.0f);

            float x0f = floorf(xs), y0f = floorf(ys);
            fx[i] = xs - x0f;
            fy[i] = ys - y0f;
            int x0 = (int)x0f, y0 = (int)y0f;
            dx[i]  = (x0 < WW - 1) ? 1 : 0;
            dyW[i] = (y0 < HH - 1) ? WW : 0;
            i00[i] = base + y0 * WW + x0;
        }

        // ---- prefetch next iteration's coherent loads (overlaps gather epoch) ----
        const int qn = q + stride;
        float4 dep4n = dep4;
        int mbn = 0;
        if (qn < nq) {
            dep4n = __ldcs(dsv + qn);
            mbn = load_mask_bits(ms, mode, base, qn);
        }

        // ---- batched depth gathers (16 back-to-back, mask-folded sentinel) ----
        float g00[4], g01[4], g10[4], g11[4];
        #pragma unroll
        for (int i = 0; i < 4; i++) {
            if (mb & (1 << i)) {
                int a00 = i00[i];
                int a10 = a00 + dyW[i];
                g00[i] = __ldg(dd + a00);
                g01[i] = __ldg(dd + a00 + dx[i]);
                g10[i] = __ldg(dd + a10);
                g11[i] = __ldg(dd + a10 + dx[i]);
            } else {
                g00[i] = g01[i] = g10[i] = g11[i] = 1e30f;
            }
        }

        // ---- clamp test + sparse (≈13%) predicated RGB work ----
        #pragma unroll
        for (int i = 0; i < 4; i++) {
            float ofx = 1.0f - fx[i], ofy = 1.0f - fy[i];
            float w00 = ofx*ofy, w01 = fx[i]*ofy, w10 = ofx*fy[i], w11 = fx[i]*fy[i];
            float dsm = w00*g00[i] + w01*g01[i] + w10*g10[i] + w11*g11[i];
            float ld = fabsf(Z[i] - dsm);
            if (ld < 0.1f) {               // sentinel 1e30 auto-fails
                sd += ld;
                int a00 = i00[i] - base;
                int a10 = a00 + dyW[i];
                int p = p0 + i;
                float lr = 0.0f;
                #pragma unroll
                for (int cch = 0; cch < 3; cch++) {
                    const int o = base3 + cch * NPIX;
                    float sv = __ldcs(rs + o + p);
                    const float* ch = rd + o;
                    float sm = w00*__ldg(ch + a00)       + w01*__ldg(ch + a00 + dx[i])
                             + w10*__ldg(ch + a10)       + w11*__ldg(ch + a10 + dx[i]);
                    lr += fabsf(sv - sm);
                }
                sr += lr * (1.0f / 3.0f);
            }
        }

        dep4 = dep4n;
        mb = mbn;
        q = qn;
    }

    sd = warp_sum(sd);
    sr = warp_sum(sr);
    __shared__ float sD[8], sR[8];
    int lane = threadIdx.x & 31, wid = threadIdx.x >> 5;
    if (lane == 0) { sD[wid] = sd; sR[wid] = sr; }
    __syncthreads();
    if (threadIdx.x == 0) {
        float td = 0.0f, tr = 0.0f;
        #pragma unroll
        for (int i = 0; i < 8; i++) { td += sD[i]; tr += sR[i]; }
        const float invN = 1.0f / (float)NPIX;
        atomicAdd(out + b,      td * invN);
        atomicAdd(out + 16 + b, tr * invN);
    }
}

extern "C" void kernel_launch(void* const* d_in, const int* in_sizes, int n_in,
                              void* d_out, int out_size)
{
    const float* depth0 = (const float*)d_in[0];
    const float* depth1 = (const float*)d_in[1];
    const float* R0     = (const float*)d_in[2];
    const float* t0     = (const float*)d_in[3];
    const float* R1     = (const float*)d_in[4];
    const float* t1     = (const float*)d_in[5];
    const float* rgb0   = (const float*)d_in[6];
    const float* rgb1   = (const float*)d_in[7];
    const void*  mask0  = d_in[8];
    const void*  mask1  = d_in[9];
    const float* K      = (const float*)d_in[10];
    float* out = (float*)d_out;

    setup_kernel<<<1, 64>>>(R0, t0, R1, t1, K, (const unsigned int*)mask0, out, out_size);

    // 37 * 16 * 2 = 1184 blocks = exactly 2 waves at 4 blocks/SM on 148 SMs.
    dim3 grid(37, BS, 2);
    loss_kernel<<<grid, 256>>>(depth0, depth1, rgb0, rgb1, mask0, mask1, out);
}